// round 11
// baseline (speedup 1.0000x reference)
#include <cuda_runtime.h>
#include <cuda_bf16.h>
#include <cuda_fp16.h>
#include <cstdint>
#include <math.h>

#define BATCH 8
#define CIN   256
#define NTOK  4096
#define CD    128
#define NKT   64
#define LOG2E 1.4426950408889634f

// ---------------- device scratch ----------------
__device__ __nv_bfloat16 g_Xh[BATCH * CIN * NTOK];
__device__ __nv_bfloat16 g_Xl[BATCH * CIN * NTOK];
__device__ __nv_bfloat16 g_Twh[CD * CIN], g_Twl[CD * CIN];
__device__ __nv_bfloat16 g_Pwh[CD * CIN], g_Pwl[CD * CIN];
__device__ __nv_bfloat16 g_Gwh[CD * CIN], g_Gwl[CD * CIN];
__device__ __nv_bfloat16 g_Wwh[CIN * CD], g_Wwl[CIN * CD];
__device__ __nv_bfloat16 g_Qh[BATCH * NTOK * CD], g_Ql[BATCH * NTOK * CD];
__device__ __nv_bfloat16 g_Kh[BATCH * NTOK * CD], g_Kl[BATCH * NTOK * CD];
__device__ __half        g_Vh[BATCH * NTOK * CD];
__device__ __nv_bfloat16 g_Yh[BATCH * NTOK * CD], g_Yl[BATCH * NTOK * CD];

// ---------------- helpers ----------------
__device__ __forceinline__ uint32_t s2u(const void* p) {
    uint32_t a;
    asm("{ .reg .u64 t; cvta.to.shared.u64 t, %1; cvt.u32.u64 %0, t; }"
        : "=r"(a) : "l"(p));
    return a;
}
__device__ __forceinline__ void ldsm4(uint32_t* r, uint32_t a) {
    asm volatile("ldmatrix.sync.aligned.m8n8.x4.shared.b16 {%0,%1,%2,%3}, [%4];"
        : "=r"(r[0]), "=r"(r[1]), "=r"(r[2]), "=r"(r[3]) : "r"(a));
}
__device__ __forceinline__ void ldsm4t(uint32_t* r, uint32_t a) {
    asm volatile("ldmatrix.sync.aligned.m8n8.x4.trans.shared.b16 {%0,%1,%2,%3}, [%4];"
        : "=r"(r[0]), "=r"(r[1]), "=r"(r[2]), "=r"(r[3]) : "r"(a));
}
__device__ __forceinline__ void mma_bf(float* d, const uint32_t* a, uint32_t b0, uint32_t b1) {
    asm volatile(
        "mma.sync.aligned.m16n8k16.row.col.f32.bf16.bf16.f32 "
        "{%0,%1,%2,%3},{%4,%5,%6,%7},{%8,%9},{%0,%1,%2,%3};"
        : "+f"(d[0]), "+f"(d[1]), "+f"(d[2]), "+f"(d[3])
        : "r"(a[0]), "r"(a[1]), "r"(a[2]), "r"(a[3]), "r"(b0), "r"(b1));
}
__device__ __forceinline__ void mma_hf(float* d, const uint32_t* a, uint32_t b0, uint32_t b1) {
    asm volatile(
        "mma.sync.aligned.m16n8k16.row.col.f32.f16.f16.f32 "
        "{%0,%1,%2,%3},{%4,%5,%6,%7},{%8,%9},{%0,%1,%2,%3};"
        : "+f"(d[0]), "+f"(d[1]), "+f"(d[2]), "+f"(d[3])
        : "r"(a[0]), "r"(a[1]), "r"(a[2]), "r"(a[3]), "r"(b0), "r"(b1));
}
__device__ __forceinline__ void cp16(uint32_t dst, const void* src) {
    asm volatile("cp.async.cg.shared.global [%0], [%1], 16;" :: "r"(dst), "l"(src));
}
__device__ __forceinline__ void cp_commit() { asm volatile("cp.async.commit_group;"); }
__device__ __forceinline__ void cp_wait1() { asm volatile("cp.async.wait_group 1;" ::: "memory"); }
__device__ __forceinline__ void cp_wait0() { asm volatile("cp.async.wait_group 0;" ::: "memory"); }

__device__ __forceinline__ uint32_t swz(int r, int c16) {
    return (uint32_t)(r * 256 + ((c16 ^ (r & 7)) << 4));
}
__device__ __forceinline__ uint32_t swzB(int r, int c16) {
    return (uint32_t)(r * 128 + ((c16 ^ (r & 7)) << 4));
}

// MUFU exp2 (inputs arrive pre-scaled by log2e via Q scaling)
__device__ __forceinline__ float ex2(float x) {
    float y;
    asm("ex2.approx.ftz.f32 %0, %1;" : "=f"(y) : "f"(x));
    return y;
}

__device__ __forceinline__ void bfsplit(float v, unsigned short& h, unsigned short& l) {
    __nv_bfloat16 bh = __float2bfloat16_rn(v);
    __nv_bfloat16 bl = __float2bfloat16_rn(v - __bfloat162float(bh));
    h = __bfloat16_as_ushort(bh);
    l = __bfloat16_as_ushort(bl);
}
__device__ __forceinline__ void split2(float x, float y, uint32_t& h, uint32_t& l) {
    unsigned short hx, lx, hy, ly;
    bfsplit(x, hx, lx);
    bfsplit(y, hy, ly);
    h = (uint32_t)hx | ((uint32_t)hy << 16);
    l = (uint32_t)lx | ((uint32_t)ly << 16);
}
// pack (lo_elem, hi_elem) -> f16x2
__device__ __forceinline__ uint32_t pack_h2(float lo, float hi) {
    uint32_t r;
    asm("cvt.rn.f16x2.f32 %0, %1, %2;" : "=r"(r) : "f"(hi), "f"(lo));
    return r;
}

// ---------------------------------------------------------------------------
// conversion passes
// ---------------------------------------------------------------------------
__global__ __launch_bounds__(256) void conv_x_kernel(const float* __restrict__ x)
{
    size_t i = ((size_t)blockIdx.x * 256 + threadIdx.x) * 4;
    float4 v = *(const float4*)&x[i];
    unsigned short h[4], l[4];
    bfsplit(v.x, h[0], l[0]); bfsplit(v.y, h[1], l[1]);
    bfsplit(v.z, h[2], l[2]); bfsplit(v.w, h[3], l[3]);
    *(uint2*)&g_Xh[i] = make_uint2((unsigned)h[0] | ((unsigned)h[1] << 16),
                                   (unsigned)h[2] | ((unsigned)h[3] << 16));
    *(uint2*)&g_Xl[i] = make_uint2((unsigned)l[0] | ((unsigned)l[1] << 16),
                                   (unsigned)l[2] | ((unsigned)l[3] << 16));
}

__global__ __launch_bounds__(256) void conv_w_kernel(
    const float* __restrict__ tw, const float* __restrict__ pw,
    const float* __restrict__ gw, const float* __restrict__ ww)
{
    const float* src; __nv_bfloat16* dh; __nv_bfloat16* dl;
    switch (blockIdx.y) {
        case 0: src = tw; dh = g_Twh; dl = g_Twl; break;
        case 1: src = pw; dh = g_Pwh; dl = g_Pwl; break;
        case 2: src = gw; dh = g_Gwh; dl = g_Gwl; break;
        default: src = ww; dh = g_Wwh; dl = g_Wwl; break;
    }
    size_t i = ((size_t)blockIdx.x * 256 + threadIdx.x) * 4;
    float4 v = *(const float4*)&src[i];
    unsigned short h[4], l[4];
    bfsplit(v.x, h[0], l[0]); bfsplit(v.y, h[1], l[1]);
    bfsplit(v.z, h[2], l[2]); bfsplit(v.w, h[3], l[3]);
    *(uint2*)&dh[i] = make_uint2((unsigned)h[0] | ((unsigned)h[1] << 16),
                                 (unsigned)h[2] | ((unsigned)h[3] << 16));
    *(uint2*)&dl[i] = make_uint2((unsigned)l[0] | ((unsigned)l[1] << 16),
                                 (unsigned)l[2] | ((unsigned)l[3] << 16));
}

// ---------------------------------------------------------------------------
// HMMA projections. grid (32,8,3), 256 threads.
// Q output (which==0) is pre-scaled by LOG2E so S arrives in log2 domain.
// ---------------------------------------------------------------------------
#define PS_XH(s) ((s) * 65536u)
#define PS_XL(s) ((s) * 65536u + 16384u)
#define PS_WH(s) ((s) * 65536u + 32768u)
#define PS_WL(s) ((s) * 65536u + 49152u)
#define SMEM_PROJ 131072u

__global__ __launch_bounds__(256, 1) void proj_mma_kernel(
    const float* __restrict__ tb, const float* __restrict__ pb,
    const float* __restrict__ gb)
{
    extern __shared__ __align__(256) char sm[];
    const uint32_t su = s2u(sm);

    const int t = threadIdx.x;
    const int w = t >> 5;
    const int lane = t & 31;
    const int sub = lane >> 3;
    const int rowInM = lane & 7;
    const int b = blockIdx.y;
    const int which = blockIdx.z;
    const int n0 = blockIdx.x * 128;

    const __nv_bfloat16 *wh, *wl; const float* bias;
    if (which == 0)      { wh = g_Twh; wl = g_Twl; bias = tb; }
    else if (which == 1) { wh = g_Pwh; wl = g_Pwl; bias = pb; }
    else                 { wh = g_Gwh; wl = g_Gwl; bias = gb; }
    const __nv_bfloat16* xh = g_Xh + (size_t)b * CIN * NTOK;
    const __nv_bfloat16* xl = g_Xl + (size_t)b * CIN * NTOK;

    auto load_stage = [&](int c0, int s) {
        for (int i = t; i < 1024; i += 256) {
            int r = i >> 4, ch = i & 15;
            uint32_t off = swz(r, ch);
            size_t g = (size_t)(c0 + r) * NTOK + n0 + ch * 8;
            cp16(su + PS_XH(s) + off, xh + g);
            cp16(su + PS_XL(s) + off, xl + g);
        }
        for (int i = t; i < 1024; i += 256) {
            int r = i >> 3, ch = i & 7;
            uint32_t off = swzB(r, ch);
            size_t g = (size_t)r * CIN + c0 + ch * 8;
            cp16(su + PS_WH(s) + off, wh + g);
            cp16(su + PS_WL(s) + off, wl + g);
        }
    };

    float d[16][4];
    #pragma unroll
    for (int i = 0; i < 16; i++)
        #pragma unroll
        for (int j = 0; j < 4; j++) d[i][j] = 0.f;

    load_stage(0, 0);
    cp_commit();

    for (int ck = 0; ck < 4; ck++) {
        if (ck < 3) { load_stage((ck + 1) * 64, (ck + 1) & 1); cp_commit(); cp_wait1(); }
        else cp_wait0();
        __syncthreads();
        const int s = ck & 1;
        #pragma unroll
        for (int kc = 0; kc < 4; kc++) {
            uint32_t ah[4], al[4];
            {
                int row = kc * 16 + rowInM + ((sub >> 1) << 3);
                int c16 = w * 2 + (sub & 1);
                ldsm4t(ah, su + PS_XH(s) + swz(row, c16));
                ldsm4t(al, su + PS_XL(s) + swz(row, c16));
            }
            #pragma unroll
            for (int nbp = 0; nbp < 8; nbp++) {
                uint32_t bh[4], bl[4];
                int row = nbp * 16 + rowInM + ((sub >> 1) << 3);
                int c16 = kc * 2 + (sub & 1);
                ldsm4(bh, su + PS_WH(s) + swzB(row, c16));
                ldsm4(bl, su + PS_WL(s) + swzB(row, c16));
                mma_bf(d[nbp * 2],     ah, bh[0], bh[1]);
                mma_bf(d[nbp * 2],     ah, bl[0], bl[1]);
                mma_bf(d[nbp * 2],     al, bh[0], bh[1]);
                mma_bf(d[nbp * 2 + 1], ah, bh[2], bh[3]);
                mma_bf(d[nbp * 2 + 1], ah, bl[2], bl[3]);
                mma_bf(d[nbp * 2 + 1], al, bh[2], bh[3]);
            }
        }
        __syncthreads();
    }

    const int g = lane >> 2, tq = lane & 3;
    const size_t nlo = (size_t)(n0 + w * 16 + g);
    const size_t nhi = nlo + 8;
    const float sc = (which == 0) ? LOG2E : 1.f;
    if (which < 2) {
        __nv_bfloat16* oh = (which == 0 ? g_Qh : g_Kh) + (size_t)b * NTOK * CD;
        __nv_bfloat16* ol = (which == 0 ? g_Ql : g_Kl) + (size_t)b * NTOK * CD;
        #pragma unroll
        for (int nb = 0; nb < 16; nb++) {
            int k0 = nb * 8 + tq * 2;
            float2 bb = *(const float2*)&bias[k0];
            uint32_t h, l;
            split2((d[nb][0] + bb.x) * sc, (d[nb][1] + bb.y) * sc, h, l);
            *(uint32_t*)&oh[nlo * CD + k0] = h;
            *(uint32_t*)&ol[nlo * CD + k0] = l;
            split2((d[nb][2] + bb.x) * sc, (d[nb][3] + bb.y) * sc, h, l);
            *(uint32_t*)&oh[nhi * CD + k0] = h;
            *(uint32_t*)&ol[nhi * CD + k0] = l;
        }
    } else {
        __half* oh = g_Vh + (size_t)b * NTOK * CD;
        #pragma unroll
        for (int nb = 0; nb < 16; nb++) {
            int k0 = nb * 8 + tq * 2;
            float2 bb = *(const float2*)&bias[k0];
            *(uint32_t*)&oh[nlo * CD + k0] = pack_h2(d[nb][0] + bb.x, d[nb][1] + bb.y);
            *(uint32_t*)&oh[nhi * CD + k0] = pack_h2(d[nb][2] + bb.x, d[nb][3] + bb.y);
        }
    }
}

// ---------------------------------------------------------------------------
// HMMA flash attention. BQ=64, BK=64. grid (64, 8), 128 threads, 2 CTAs/SM.
// Pipelined: per tile kt issue S(kt) MMA, then PV(kt-1) MMA, then softmax(kt);
// softmax ALU overlaps the PV tensor drain. V ring = 3 stages, K = 2 stages.
// smem: KH 2x16K @0, KL 2x16K @32K, V 3x16K @64K = 112 KB.
// ---------------------------------------------------------------------------
#define S_KH 0u
#define S_KL 32768u
#define S_VH 65536u
#define S_STG 16384u
#define SMEM_FLASH 114688u

__global__ __launch_bounds__(128, 2) void flash_mma_kernel()
{
    extern __shared__ __align__(256) char sm[];
    const uint32_t su = s2u(sm);

    const int t = threadIdx.x;
    const int w = t >> 5;
    const int lane = t & 31;
    const int sub = lane >> 3;
    const int rowInM = lane & 7;
    const int b = blockIdx.y;
    const int q0 = blockIdx.x * 64;

    const __nv_bfloat16* Qhg = g_Qh + ((size_t)b * NTOK + q0) * CD;
    const __nv_bfloat16* Qlg = g_Ql + ((size_t)b * NTOK + q0) * CD;
    const __nv_bfloat16* Khg = g_Kh + (size_t)b * NTOK * CD;
    const __nv_bfloat16* Klg = g_Kl + (size_t)b * NTOK * CD;
    const __half* Vhg = g_Vh + (size_t)b * NTOK * CD;

    // ---- stage Q through the K buffers, pull fragments to registers ----
    for (int i = t; i < 1024; i += 128) {
        int r = i >> 4, c = i & 15;
        uint32_t off = swz(r, c);
        cp16(su + S_KH + off,         Qhg + (size_t)r * CD + c * 8);
        cp16(su + S_KH + S_STG + off, Qlg + (size_t)r * CD + c * 8);
    }
    cp_commit(); cp_wait0();
    __syncthreads();

    uint32_t qh[8][4], ql[8][4];
    #pragma unroll
    for (int kc = 0; kc < 8; kc++) {
        int row = w * 16 + rowInM + ((sub & 1) << 3);
        int c16 = kc * 2 + (sub >> 1);
        ldsm4(qh[kc], su + S_KH + swz(row, c16));
        ldsm4(ql[kc], su + S_KH + S_STG + swz(row, c16));
    }
    __syncthreads();

    // ---- prefetch kt=0 ----
    for (int i = t; i < 1024; i += 128) {
        int r = i >> 4, c = i & 15;
        uint32_t off = swz(r, c);
        size_t g = (size_t)r * CD + c * 8;
        cp16(su + S_KH + off, Khg + g);
        cp16(su + S_KL + off, Klg + g);
        cp16(su + S_VH + off, Vhg + g);
    }
    cp_commit();

    float o[16][4];
    #pragma unroll
    for (int f = 0; f < 16; f++)
        #pragma unroll
        for (int j = 0; j < 4; j++) o[f][j] = 0.f;
    float m0 = -1e30f, m1 = -1e30f, l0 = 0.f, l1 = 0.f;
    uint32_t php0[8], php1[8];   // P of previous tile

    for (int kt = 0; kt < NKT; kt++) {
        const uint32_t st  = (kt & 1) * S_STG;
        const uint32_t vpv = (uint32_t)(((kt + 2) % 3)) * S_STG;  // (kt-1)%3
        if (kt + 1 < NKT) {
            const uint32_t stk = ((kt + 1) & 1) * S_STG;
            const uint32_t stv = (uint32_t)((kt + 1) % 3) * S_STG;
            const size_t gofs = (size_t)(kt + 1) * 64 * CD;
            for (int i = t; i < 1024; i += 128) {
                int r = i >> 4, c = i & 15;
                uint32_t off = swz(r, c);
                size_t g = gofs + (size_t)r * CD + c * 8;
                cp16(su + S_KH + stk + off, Khg + g);
                cp16(su + S_KL + stk + off, Klg + g);
                cp16(su + S_VH + stv + off, Vhg + g);
            }
            cp_commit();
            cp_wait1();
        } else {
            cp_wait0();
        }
        __syncthreads();

        // ---------- S = Q K^T (bf16, 3 products; Q from registers) ----------
        float s[8][4];
        #pragma unroll
        for (int f = 0; f < 8; f++)
            #pragma unroll
            for (int j = 0; j < 4; j++) s[f][j] = 0.f;

        #pragma unroll
        for (int kc = 0; kc < 8; kc++) {
            #pragma unroll
            for (int nb = 0; nb < 4; nb++) {
                uint32_t kh4[4], kl4[4];
                int row = nb * 16 + rowInM + ((sub >> 1) << 3);
                int c16 = kc * 2 + (sub & 1);
                ldsm4(kh4, su + S_KH + st + swz(row, c16));
                ldsm4(kl4, su + S_KL + st + swz(row, c16));
                mma_bf(s[nb * 2],     qh[kc], kh4[0], kh4[1]);
                mma_bf(s[nb * 2 + 1], qh[kc], kh4[2], kh4[3]);
                mma_bf(s[nb * 2],     qh[kc], kl4[0], kl4[1]);
                mma_bf(s[nb * 2 + 1], qh[kc], kl4[2], kl4[3]);
                mma_bf(s[nb * 2],     ql[kc], kh4[0], kh4[1]);
                mma_bf(s[nb * 2 + 1], ql[kc], kh4[2], kh4[3]);
            }
        }

        // ---------- O += P(kt-1) V(kt-1): fills tensor pipe under softmax ----------
        if (kt > 0) {
            #pragma unroll
            for (int kc = 0; kc < 4; kc++) {
                uint32_t a[4] = {php0[kc * 2], php1[kc * 2],
                                 php0[kc * 2 + 1], php1[kc * 2 + 1]};
                int row = kc * 16 + rowInM + ((sub & 1) << 3);
                #pragma unroll
                for (int vb = 0; vb < 8; vb++) {
                    int c16 = vb * 2 + (sub >> 1);
                    uint32_t vh4[4];
                    ldsm4t(vh4, su + S_VH + vpv + swz(row, c16));
                    mma_hf(o[vb * 2],     a, vh4[0], vh4[1]);
                    mma_hf(o[vb * 2 + 1], a, vh4[2], vh4[3]);
                }
            }
        }

        // ---------- online softmax in log2 domain (overlaps PV drain) ----------
        float mx0 = -1e30f, mx1 = -1e30f;
        #pragma unroll
        for (int f = 0; f < 8; f++) {
            mx0 = fmaxf(mx0, fmaxf(s[f][0], s[f][1]));
            mx1 = fmaxf(mx1, fmaxf(s[f][2], s[f][3]));
        }
        mx0 = fmaxf(mx0, __shfl_xor_sync(0xffffffffu, mx0, 1));
        mx0 = fmaxf(mx0, __shfl_xor_sync(0xffffffffu, mx0, 2));
        mx1 = fmaxf(mx1, __shfl_xor_sync(0xffffffffu, mx1, 1));
        mx1 = fmaxf(mx1, __shfl_xor_sync(0xffffffffu, mx1, 2));

        uint32_t upd = __ballot_sync(0xffffffffu, (mx0 > m0) || (mx1 > m1));
        if (upd) {
            float mn0 = fmaxf(m0, mx0), mn1 = fmaxf(m1, mx1);
            float c0f = ex2(m0 - mn0), c1f = ex2(m1 - mn1);
            m0 = mn0; m1 = mn1;
            l0 *= c0f; l1 *= c1f;
            #pragma unroll
            for (int f = 0; f < 16; f++) {
                o[f][0] *= c0f; o[f][1] *= c0f;
                o[f][2] *= c1f; o[f][3] *= c1f;
            }
        }

        float ps0 = 0.f, ps1 = 0.f;
        #pragma unroll
        for (int f = 0; f < 8; f++) {
            float p00 = ex2(s[f][0] - m0);
            float p01 = ex2(s[f][1] - m0);
            float p10 = ex2(s[f][2] - m1);
            float p11 = ex2(s[f][3] - m1);
            ps0 += p00 + p01;
            ps1 += p10 + p11;
            php0[f] = pack_h2(p00, p01);
            php1[f] = pack_h2(p10, p11);
        }
        ps0 += __shfl_xor_sync(0xffffffffu, ps0, 1);
        ps0 += __shfl_xor_sync(0xffffffffu, ps0, 2);
        ps1 += __shfl_xor_sync(0xffffffffu, ps1, 1);
        ps1 += __shfl_xor_sync(0xffffffffu, ps1, 2);
        l0 += ps0;
        l1 += ps1;

        __syncthreads();
    }

    // ---------- final PV(63) ----------
    {
        const uint32_t vpv = (uint32_t)((NKT - 1) % 3) * S_STG;
        #pragma unroll
        for (int kc = 0; kc < 4; kc++) {
            uint32_t a[4] = {php0[kc * 2], php1[kc * 2],
                             php0[kc * 2 + 1], php1[kc * 2 + 1]};
            int row = kc * 16 + rowInM + ((sub & 1) << 3);
            #pragma unroll
            for (int vb = 0; vb < 8; vb++) {
                int c16 = vb * 2 + (sub >> 1);
                uint32_t vh4[4];
                ldsm4t(vh4, su + S_VH + vpv + swz(row, c16));
                mma_hf(o[vb * 2],     a, vh4[0], vh4[1]);
                mma_hf(o[vb * 2 + 1], a, vh4[2], vh4[3]);
            }
        }
    }

    // ---------- normalize + store Y (bf16 hi/lo) ----------
    const float i0 = 1.f / l0, i1 = 1.f / l1;
    const int g = lane >> 2, tq = lane & 3;
    const size_t r0 = (size_t)b * NTOK + q0 + w * 16 + g;
    const size_t r1 = r0 + 8;
    #pragma unroll
    for (int f = 0; f < 16; f++) {
        int col = f * 8 + tq * 2;
        uint32_t h, l;
        split2(o[f][0] * i0, o[f][1] * i0, h, l);
        *(uint32_t*)&g_Yh[r0 * CD + col] = h;
        *(uint32_t*)&g_Yl[r0 * CD + col] = l;
        split2(o[f][2] * i1, o[f][3] * i1, h, l);
        *(uint32_t*)&g_Yh[r1 * CD + col] = h;
        *(uint32_t*)&g_Yl[r1 * CD + col] = l;
    }
}

// ---------------------------------------------------------------------------
// HMMA output conv. grid (32 n, 2 c, 8 b), 256 threads.
// ---------------------------------------------------------------------------
#define OS_WH 0u
#define OS_WL 32768u
#define OS_YH 65536u
#define OS_YL 98304u
#define SMEM_OUT 131072u

__global__ __launch_bounds__(256, 1) void out_mma_kernel(
    const float* __restrict__ wb, float* __restrict__ out)
{
    extern __shared__ __align__(256) char sm[];
    const uint32_t su = s2u(sm);

    const int t = threadIdx.x;
    const int w = t >> 5;
    const int lane = t & 31;
    const int sub = lane >> 3;
    const int rowInM = lane & 7;
    const int b = blockIdx.z;
    const int c0t = blockIdx.y * 128;
    const int n0 = blockIdx.x * 128;

    for (int i = t; i < 2048; i += 256) {
        int r = i >> 4, ch = i & 15;
        uint32_t off = swz(r, ch);
        size_t gw = (size_t)(c0t + r) * CD + ch * 8;
        size_t gy = ((size_t)b * NTOK + n0 + r) * CD + ch * 8;
        cp16(su + OS_WH + off, g_Wwh + gw);
        cp16(su + OS_WL + off, g_Wwl + gw);
        cp16(su + OS_YH + off, g_Yh + gy);
        cp16(su + OS_YL + off, g_Yl + gy);
    }
    cp_commit();
    cp_wait0();
    __syncthreads();

    float d[16][4];
    #pragma unroll
    for (int i = 0; i < 16; i++)
        #pragma unroll
        for (int j = 0; j < 4; j++) d[i][j] = 0.f;

    #pragma unroll
    for (int kc = 0; kc < 8; kc++) {
        uint32_t ah[4], al[4];
        {
            int row = w * 16 + rowInM + ((sub & 1) << 3);
            int c16 = kc * 2 + (sub >> 1);
            ldsm4(ah, su + OS_WH + swz(row, c16));
            ldsm4(al, su + OS_WL + swz(row, c16));
        }
        #pragma unroll
        for (int nbp = 0; nbp < 8; nbp++) {
            uint32_t yh[4], yl[4];
            int row = nbp * 16 + rowInM + ((sub >> 1) << 3);
            int c16 = kc * 2 + (sub & 1);
            ldsm4(yh, su + OS_YH + swz(row, c16));
            ldsm4(yl, su + OS_YL + swz(row, c16));
            mma_bf(d[nbp * 2],     ah, yh[0], yh[1]);
            mma_bf(d[nbp * 2],     ah, yl[0], yl[1]);
            mma_bf(d[nbp * 2],     al, yh[0], yh[1]);
            mma_bf(d[nbp * 2 + 1], ah, yh[2], yh[3]);
            mma_bf(d[nbp * 2 + 1], ah, yl[2], yl[3]);
            mma_bf(d[nbp * 2 + 1], al, yh[2], yh[3]);
        }
    }

    const int g = lane >> 2, tq = lane & 3;
    const int clo = c0t + w * 16 + g;
    const int chi = clo + 8;
    const float wb0 = wb[clo], wb1 = wb[chi];
    float* ob = out + (size_t)b * CIN * NTOK;
    #pragma unroll
    for (int nb = 0; nb < 16; nb++) {
        int n = n0 + nb * 8 + tq * 2;
        *(float2*)&ob[(size_t)clo * NTOK + n] = make_float2(d[nb][0] + wb0, d[nb][1] + wb0);
        *(float2*)&ob[(size_t)chi * NTOK + n] = make_float2(d[nb][2] + wb1, d[nb][3] + wb1);
    }
}

// ---------------------------------------------------------------------------
extern "C" void kernel_launch(void* const* d_in, const int* in_sizes, int n_in,
                              void* d_out, int out_size)
{
    const float* x  = (const float*)d_in[0];
    const float* tw = (const float*)d_in[1];
    const float* tb = (const float*)d_in[2];
    const float* pw = (const float*)d_in[3];
    const float* pb = (const float*)d_in[4];
    const float* gw = (const float*)d_in[5];
    const float* gb = (const float*)d_in[6];
    const float* ww = (const float*)d_in[7];
    const float* wb = (const float*)d_in[8];
    float* out = (float*)d_out;
    (void)in_sizes; (void)n_in; (void)out_size;

    conv_x_kernel<<<(BATCH * CIN * NTOK) / 1024, 256>>>(x);
    conv_w_kernel<<<dim3((CD * CIN) / 1024, 4), 256>>>(tw, pw, gw, ww);

    cudaFuncSetAttribute(proj_mma_kernel,
                         cudaFuncAttributeMaxDynamicSharedMemorySize, SMEM_PROJ);
    proj_mma_kernel<<<dim3(NTOK / 128, BATCH, 3), 256, SMEM_PROJ>>>(tb, pb, gb);

    cudaFuncSetAttribute(flash_mma_kernel,
                         cudaFuncAttributeMaxDynamicSharedMemorySize, SMEM_FLASH);
    flash_mma_kernel<<<dim3(NTOK / 64, BATCH), 128, SMEM_FLASH>>>();

    cudaFuncSetAttribute(out_mma_kernel,
                         cudaFuncAttributeMaxDynamicSharedMemorySize, SMEM_OUT);
    out_mma_kernel<<<dim3(NTOK / 128, CIN / 128, BATCH), 256, SMEM_OUT>>>(wb, out);
}